// round 1
// baseline (speedup 1.0000x reference)
#include <cuda_runtime.h>
#include <math.h>

#define Nn 512
#define Cc 128
#define Hh 8
#define Bb 2
#define NN (Nn*Nn)

// Scratch (device globals: allowed; no runtime allocation)
__device__ float g_Vin [Bb*Hh*NN];
__device__ float g_Vout[Bb*Hh*NN];
__device__ float g_Ein [Bb*Hh*NN];
__device__ float g_Eo  [Bb*Hh*NN];
__device__ float g_VaIn [Bb*Hh*NN];
__device__ float g_VaOut[Bb*Hh*NN];

__device__ __forceinline__ float sigmoidf_(float x){ return 1.f/(1.f + __expf(-x)); }

// ---------------------------------------------------------------------------
// Stage A: LayerNorm + (Wv,We) projections + siglin gating.
// Block: 256 threads handles (b, i0, j0..j0+31). All 4 gated tensors are
// written in [b,h,row,col] layout with coalesced stores (no transposes needed
// because the "out" einsum is done as a TN GEMM in stage B).
// ---------------------------------------------------------------------------
__global__ __launch_bounds__(256) void ka_ln_proj_gate(
    const float* __restrict__ e, const float* __restrict__ mask,
    const float* __restrict__ lnw, const float* __restrict__ lnb,
    const float* __restrict__ Wv, const float* __restrict__ bv,
    const float* __restrict__ We, const float* __restrict__ be)
{
    __shared__ float eln[128][33];     // [c][r], padded
    __shared__ float red[2][8][32];
    __shared__ float smu[32], srs[32];

    const int t  = threadIdx.x;
    const int b  = blockIdx.z;
    const int i0 = blockIdx.y;
    const int j0 = blockIdx.x * 32;
    const int rowbase = (b*Nn + i0)*Nn + j0;

    // Load e tile [32 rows x 128 c], transpose into smem
    const float4* e4 = reinterpret_cast<const float4*>(e);
    #pragma unroll
    for (int q = 0; q < 4; q++){
        int idx = q*256 + t;
        int r = idx >> 5, c4 = idx & 31;
        float4 v = e4[(rowbase + r)*32 + c4];
        eln[c4*4+0][r]=v.x; eln[c4*4+1][r]=v.y; eln[c4*4+2][r]=v.z; eln[c4*4+3][r]=v.w;
    }
    __syncthreads();

    // Row stats (mean/var over C=128)
    {
        int r = t & 31, g8 = t >> 5;
        float s=0.f, sq=0.f;
        #pragma unroll
        for (int q = 0; q < 16; q++){ float x = eln[g8*16+q][r]; s += x; sq += x*x; }
        red[0][g8][r]=s; red[1][g8][r]=sq;
    }
    __syncthreads();
    if (t < 32){
        float s=0.f, sq=0.f;
        #pragma unroll
        for (int g8 = 0; g8 < 8; g8++){ s += red[0][g8][t]; sq += red[1][g8][t]; }
        float mu  = s * (1.f/128.f);
        float var = sq * (1.f/128.f) - mu*mu;
        smu[t] = mu;
        srs[t] = rsqrtf(var + 1e-5f);
    }
    __syncthreads();

    // Normalize in place (apply ln_w / ln_b)
    #pragma unroll
    for (int q = 0; q < 16; q++){
        int idx = q*256 + t;
        int c = idx >> 5, r = idx & 31;
        eln[c][r] = (eln[c][r] - smu[r]) * srs[r] * lnw[c] + lnb[c];
    }
    __syncthreads();

    // Projection: thread (r, a2): r = row-in-tile, a2 selects (array, h-half).
    // arrays: 0=V_in, 1=V_out, 2=E_in, 3=E_out; each uses (g,l) column pairs.
    const int r   = t & 31;
    const int a2  = t >> 5;           // 0..7
    const int a   = a2 >> 1;          // 0..3
    const int hh  = (a2 & 1) * 4;     // head offset 0 or 4
    const float* Wbase = (a < 2) ? Wv : We;      // [128 x 32] row-major
    const float* bbase = (a < 2) ? bv : be;
    const int gcol = (a & 1)*16 + hh;            // g columns gcol..gcol+3
    const int lcol = gcol + 8;                   // l columns

    float accg[4] = {0.f,0.f,0.f,0.f};
    float accl[4] = {0.f,0.f,0.f,0.f};
    #pragma unroll 8
    for (int c = 0; c < 128; c++){
        float x = eln[c][r];
        float4 wg = *reinterpret_cast<const float4*>(&Wbase[c*32 + gcol]);
        float4 wl = *reinterpret_cast<const float4*>(&Wbase[c*32 + lcol]);
        accg[0] = fmaf(x, wg.x, accg[0]);
        accg[1] = fmaf(x, wg.y, accg[1]);
        accg[2] = fmaf(x, wg.z, accg[2]);
        accg[3] = fmaf(x, wg.w, accg[3]);
        accl[0] = fmaf(x, wl.x, accl[0]);
        accl[1] = fmaf(x, wl.y, accl[1]);
        accl[2] = fmaf(x, wl.z, accl[2]);
        accl[3] = fmaf(x, wl.w, accl[3]);
    }

    float mk = mask[rowbase + r];
    float* dst = (a==0) ? g_Vin : (a==1) ? g_Vout : (a==2) ? g_Ein : g_Eo;
    const int obase = (b*Hh)*NN + i0*Nn + j0 + r;
    #pragma unroll
    for (int u = 0; u < 4; u++){
        float g = accg[u] + bbase[gcol+u] + mk;
        float l = accl[u] + bbase[lcol+u];
        dst[obase + (hh+u)*NN] = sigmoidf_(g) * l;
    }
}

// ---------------------------------------------------------------------------
// Stage B: 32 independent 512x512x512 fp32 GEMMs.
//   typ=0 (NT): VaIn[i,j]  = sum_k Ein[i,k] * Vin[j,k]
//   typ=1 (TN): VaOut[i,j] = sum_k Eo[k,i]  * Vout[k,j]
// 128x128 tile, KB=8, 8x8 per thread, register-prefetch double-buffered smem,
// one barrier per K-step.
// ---------------------------------------------------------------------------
__global__ __launch_bounds__(256) void kb_gemm()
{
    const int z   = blockIdx.z;
    const int typ = z >> 4;        // 0 in / 1 out
    const int mh  = z & 15;        // b*8+h
    const float* __restrict__ A  = (typ ? g_Eo   : g_Ein ) + mh*NN;
    const float* __restrict__ Bm = (typ ? g_Vout : g_Vin ) + mh*NN;
    float*       __restrict__ C  = (typ ? g_VaOut: g_VaIn) + mh*NN;
    const int it = blockIdx.y * 128;
    const int jt = blockIdx.x * 128;

    __shared__ __align__(16) float As[2][8][132];
    __shared__ __align__(16) float Bs[2][8][132];

    const int t  = threadIdx.x;
    const int tx = t & 15, ty = t >> 4;

    float acc[8][8];
    #pragma unroll
    for (int u = 0; u < 8; u++)
        #pragma unroll
        for (int v = 0; v < 8; v++) acc[u][v] = 0.f;

    const int kk_l = t >> 5, i4_l = (t & 31) << 2;   // TN loader indices
    const int ii_l = t >> 1, k4_l = (t & 1) << 2;    // NT loader indices

    float4 ra, rb;
    // Prologue: tile k0=0 into buffer 0
    if (typ){
        ra = *reinterpret_cast<const float4*>(&A [kk_l*Nn + it + i4_l]);
        rb = *reinterpret_cast<const float4*>(&Bm[kk_l*Nn + jt + i4_l]);
        *reinterpret_cast<float4*>(&As[0][kk_l][i4_l]) = ra;
        *reinterpret_cast<float4*>(&Bs[0][kk_l][i4_l]) = rb;
    } else {
        ra = *reinterpret_cast<const float4*>(&A [(it+ii_l)*Nn + k4_l]);
        rb = *reinterpret_cast<const float4*>(&Bm[(jt+ii_l)*Nn + k4_l]);
        As[0][k4_l+0][ii_l]=ra.x; As[0][k4_l+1][ii_l]=ra.y; As[0][k4_l+2][ii_l]=ra.z; As[0][k4_l+3][ii_l]=ra.w;
        Bs[0][k4_l+0][ii_l]=rb.x; Bs[0][k4_l+1][ii_l]=rb.y; Bs[0][k4_l+2][ii_l]=rb.z; Bs[0][k4_l+3][ii_l]=rb.w;
    }
    __syncthreads();

    int buf = 0;
    for (int k0 = 0; k0 < Nn; k0 += 8){
        const bool has_next = (k0 + 8 < Nn);
        if (has_next){
            const int kn = k0 + 8;
            if (typ){
                ra = *reinterpret_cast<const float4*>(&A [(kn+kk_l)*Nn + it + i4_l]);
                rb = *reinterpret_cast<const float4*>(&Bm[(kn+kk_l)*Nn + jt + i4_l]);
            } else {
                ra = *reinterpret_cast<const float4*>(&A [(it+ii_l)*Nn + kn + k4_l]);
                rb = *reinterpret_cast<const float4*>(&Bm[(jt+ii_l)*Nn + kn + k4_l]);
            }
        }
        #pragma unroll
        for (int kk = 0; kk < 8; kk++){
            float ar[8], br[8];
            float4 a0 = *reinterpret_cast<const float4*>(&As[buf][kk][ty*8    ]);
            float4 a1 = *reinterpret_cast<const float4*>(&As[buf][kk][ty*8 + 4]);
            float4 b0 = *reinterpret_cast<const float4*>(&Bs[buf][kk][tx*8    ]);
            float4 b1 = *reinterpret_cast<const float4*>(&Bs[buf][kk][tx*8 + 4]);
            ar[0]=a0.x;ar[1]=a0.y;ar[2]=a0.z;ar[3]=a0.w;ar[4]=a1.x;ar[5]=a1.y;ar[6]=a1.z;ar[7]=a1.w;
            br[0]=b0.x;br[1]=b0.y;br[2]=b0.z;br[3]=b0.w;br[4]=b1.x;br[5]=b1.y;br[6]=b1.z;br[7]=b1.w;
            #pragma unroll
            for (int u = 0; u < 8; u++)
                #pragma unroll
                for (int v = 0; v < 8; v++)
                    acc[u][v] = fmaf(ar[u], br[v], acc[u][v]);
        }
        if (has_next){
            const int nb = buf ^ 1;
            if (typ){
                *reinterpret_cast<float4*>(&As[nb][kk_l][i4_l]) = ra;
                *reinterpret_cast<float4*>(&Bs[nb][kk_l][i4_l]) = rb;
            } else {
                As[nb][k4_l+0][ii_l]=ra.x; As[nb][k4_l+1][ii_l]=ra.y; As[nb][k4_l+2][ii_l]=ra.z; As[nb][k4_l+3][ii_l]=ra.w;
                Bs[nb][k4_l+0][ii_l]=rb.x; Bs[nb][k4_l+1][ii_l]=rb.y; Bs[nb][k4_l+2][ii_l]=rb.z; Bs[nb][k4_l+3][ii_l]=rb.w;
            }
        }
        __syncthreads();
        buf ^= 1;
    }

    #pragma unroll
    for (int u = 0; u < 8; u++){
        const int row = it + ty*8 + u;
        float4 o0 = make_float4(acc[u][0],acc[u][1],acc[u][2],acc[u][3]);
        float4 o1 = make_float4(acc[u][4],acc[u][5],acc[u][6],acc[u][7]);
        *reinterpret_cast<float4*>(&C[row*Nn + jt + tx*8    ]) = o0;
        *reinterpret_cast<float4*>(&C[row*Nn + jt + tx*8 + 4]) = o1;
    }
}

// ---------------------------------------------------------------------------
// Stage C: O = Va @ Wo + bo, out = sigmoid(O[:,:128]) * O[:,128:]
// Block: (b, i, j0..j0+31). Thread = one output column c (128 threads x 2 row
// halves); Wo columns held in registers; stores fully coalesced.
// ---------------------------------------------------------------------------
__global__ __launch_bounds__(256) void kc_out(
    const float* __restrict__ Wo, const float* __restrict__ bo,
    float* __restrict__ out)
{
    __shared__ float sVa[32][16];     // [jl][v]
    __shared__ float sWo[16][256];
    __shared__ float sbo[256];

    const int t  = threadIdx.x;
    const int b  = blockIdx.z;
    const int i  = blockIdx.y;
    const int j0 = blockIdx.x * 32;

    #pragma unroll
    for (int q = 0; q < 16; q++){
        int idx = q*256 + t;
        sWo[idx >> 8][idx & 255] = Wo[idx];
    }
    sbo[t] = bo[t];
    #pragma unroll
    for (int p = 0; p < 2; p++){
        int idx = p*256 + t;
        int v = idx >> 5, jl = idx & 31;
        const float* src = (v < 8) ? (g_VaIn  + (b*Hh + v    )*NN)
                                   : (g_VaOut + (b*Hh + v - 8)*NN);
        sVa[jl][v] = src[i*Nn + j0 + jl];
    }
    __syncthreads();

    const int c  = t & 127;
    const int rp = t >> 7;
    float wg[16], wl[16];
    #pragma unroll
    for (int v = 0; v < 16; v++){ wg[v] = sWo[v][c]; wl[v] = sWo[v][c+128]; }
    const float bg = sbo[c], bl = sbo[c+128];

    float* op = out + (size_t)((b*Nn + i)*Nn + j0) * Cc + c;
    #pragma unroll
    for (int q = 0; q < 16; q++){
        const int r = rp*16 + q;
        float g = bg, l = bl;
        #pragma unroll
        for (int v = 0; v < 16; v++){
            float va = sVa[r][v];
            g = fmaf(va, wg[v], g);
            l = fmaf(va, wl[v], l);
        }
        op[(size_t)r * Cc] = sigmoidf_(g) * l;
    }
}

// ---------------------------------------------------------------------------
extern "C" void kernel_launch(void* const* d_in, const int* in_sizes, int n_in,
                              void* d_out, int out_size)
{
    const float* e    = (const float*)d_in[0];
    const float* mask = (const float*)d_in[1];
    const float* lnw  = (const float*)d_in[2];
    const float* lnb  = (const float*)d_in[3];
    const float* Wv   = (const float*)d_in[4];
    const float* bv   = (const float*)d_in[5];
    const float* We   = (const float*)d_in[6];
    const float* be   = (const float*)d_in[7];
    const float* Wo   = (const float*)d_in[8];
    const float* bo   = (const float*)d_in[9];
    float* out = (float*)d_out;

    ka_ln_proj_gate<<<dim3(16, 512, 2), 256>>>(e, mask, lnw, lnb, Wv, bv, We, be);
    kb_gemm        <<<dim3(4, 4, 32),   256>>>();
    kc_out         <<<dim3(16, 512, 2), 256>>>(Wo, bo, out);
}

// round 2
// speedup vs baseline: 1.4384x; 1.4384x over previous
#include <cuda_runtime.h>
#include <math.h>

#define Nn 512
#define Cc 128
#define Hh 8
#define Bb 2
#define NN (Nn*Nn)

// Scratch (device globals: allowed; no runtime allocation)
__device__ float g_Vin [Bb*Hh*NN];
__device__ float g_Vout[Bb*Hh*NN];
__device__ float g_Ein [Bb*Hh*NN];
__device__ float g_Eo  [Bb*Hh*NN];
__device__ float g_VaIn [Bb*Hh*NN];
__device__ float g_VaOut[Bb*Hh*NN];

__device__ __forceinline__ float sigmoidf_(float x){ return 1.f/(1.f + __expf(-x)); }

// ---------------------------------------------------------------------------
// Stage A (fused): per-block LN stats prologue + register-blocked projection
// GEMM + gating epilogue.
// Block = 256 consecutive rows of the flattened [B*N*N, 128] input.
// Output tile = 64 columns (all of Wv|We, reordered so each thread's 4 cols
// are (g,l) pairs for 2 heads of ONE dst array).
// Per-thread: 16 rows x 4 cols, KB=16 smem chunks -> 1.25 B LDS per FMA.
// ---------------------------------------------------------------------------
__global__ __launch_bounds__(256) void ka_fused(
    const float* __restrict__ e, const float* __restrict__ mask,
    const float* __restrict__ lnw, const float* __restrict__ lnb,
    const float* __restrict__ Wv, const float* __restrict__ bv,
    const float* __restrict__ We, const float* __restrict__ be)
{
    __shared__ __align__(16) float es[16][260];   // [kk][row], padded
    __shared__ __align__(16) float ws[16][68];    // [kk][jcol]
    __shared__ float smu[256], srs[256];

    const int t  = threadIdx.x;
    const int R0 = blockIdx.x * 256;

    // --- LN stats: thread t owns row R0+t ---
    {
        const float4* erow = reinterpret_cast<const float4*>(e + (size_t)(R0 + t)*128);
        float s = 0.f, sq = 0.f;
        #pragma unroll
        for (int q = 0; q < 32; q++){
            float4 v = erow[q];
            s  += v.x + v.y + v.z + v.w;
            sq += v.x*v.x + v.y*v.y + v.z*v.z + v.w*v.w;
        }
        float mu  = s * (1.f/128.f);
        float var = sq * (1.f/128.f) - mu*mu;
        smu[t] = mu;
        srs[t] = rsqrtf(var + 1e-5f);
    }
    __syncthreads();

    const int tx = t & 15, ty = t >> 4;

    float acc[16][4];
    #pragma unroll
    for (int u = 0; u < 16; u++){
        acc[u][0]=0.f; acc[u][1]=0.f; acc[u][2]=0.f; acc[u][3]=0.f;
    }

    // --- K-chunked GEMM ---
    for (int c0 = 0; c0 < 128; c0 += 16){
        // Load + normalize e chunk (second read of e: L2-hot, block WS=131KB)
        #pragma unroll
        for (int q = 0; q < 4; q++){
            int idx = q*256 + t;
            int rl = idx >> 2, c4 = idx & 3;
            float4 v = *reinterpret_cast<const float4*>(e + (size_t)(R0+rl)*128 + c0 + c4*4);
            float mu = smu[rl], rs = srs[rl];
            float4 w4 = *reinterpret_cast<const float4*>(lnw + c0 + c4*4);
            float4 b4 = *reinterpret_cast<const float4*>(lnb + c0 + c4*4);
            es[c4*4+0][rl] = (v.x - mu)*rs*w4.x + b4.x;
            es[c4*4+1][rl] = (v.y - mu)*rs*w4.y + b4.y;
            es[c4*4+2][rl] = (v.z - mu)*rs*w4.z + b4.z;
            es[c4*4+3][rl] = (v.w - mu)*rs*w4.w + b4.w;
        }
        // Load reordered weight chunk: j = a*16 + h*2 + p
        //   a: 0=V_in 1=V_out 2=E_in 3=E_out ; p: 0=g 1=l
        #pragma unroll
        for (int q = 0; q < 4; q++){
            int idx = q*256 + t;
            int kk = idx >> 6, j = idx & 63;
            int aa = j >> 4, hh = (j >> 1) & 7, p = j & 1;
            const float* Wm = (aa < 2) ? Wv : We;
            int sc = ((aa & 1) << 4) + (p << 3) + hh;
            ws[kk][j] = Wm[(c0 + kk)*32 + sc];
        }
        __syncthreads();

        #pragma unroll
        for (int kk = 0; kk < 16; kk++){
            float4 bf = *reinterpret_cast<const float4*>(&ws[kk][tx*4]);
            float4 a0 = *reinterpret_cast<const float4*>(&es[kk][ty*16     ]);
            float4 a1 = *reinterpret_cast<const float4*>(&es[kk][ty*16 +  4]);
            float4 a2 = *reinterpret_cast<const float4*>(&es[kk][ty*16 +  8]);
            float4 a3 = *reinterpret_cast<const float4*>(&es[kk][ty*16 + 12]);
            float av[16] = {a0.x,a0.y,a0.z,a0.w, a1.x,a1.y,a1.z,a1.w,
                            a2.x,a2.y,a2.z,a2.w, a3.x,a3.y,a3.z,a3.w};
            #pragma unroll
            for (int u = 0; u < 16; u++){
                acc[u][0] = fmaf(av[u], bf.x, acc[u][0]);
                acc[u][1] = fmaf(av[u], bf.y, acc[u][1]);
                acc[u][2] = fmaf(av[u], bf.z, acc[u][2]);
                acc[u][3] = fmaf(av[u], bf.w, acc[u][3]);
            }
        }
        __syncthreads();
    }

    // --- Gating epilogue: cols (g,l) x heads (h0, h0+1) of array a ---
    const int a  = tx >> 2;
    const int h0 = (tx & 3) * 2;
    float* dst = (a==0) ? g_Vin : (a==1) ? g_Vout : (a==2) ? g_Ein : g_Eo;
    const float* bm = (a < 2) ? bv : be;
    const int sbase = (a & 1) << 4;
    const float bg0 = bm[sbase + h0],     bl0 = bm[sbase + 8 + h0];
    const float bg1 = bm[sbase + h0 + 1], bl1 = bm[sbase + 8 + h0 + 1];

    float4 o0, o1;
    float* o0p = &o0.x; float* o1p = &o1.x;
    #pragma unroll
    for (int u = 0; u < 16; u++){
        int row  = R0 + ty*16 + u;
        int bb   = row >> 18;               // NN = 2^18
        int rloc = row & (NN - 1);
        float mk = mask[row];
        o0p[u & 3] = sigmoidf_(acc[u][0] + bg0 + mk) * (acc[u][1] + bl0);
        o1p[u & 3] = sigmoidf_(acc[u][2] + bg1 + mk) * (acc[u][3] + bl1);
        if ((u & 3) == 3){
            *reinterpret_cast<float4*>(&dst[(size_t)(bb*Hh + h0    )*NN + rloc - 3]) = o0;
            *reinterpret_cast<float4*>(&dst[(size_t)(bb*Hh + h0 + 1)*NN + rloc - 3]) = o1;
        }
    }
}

// ---------------------------------------------------------------------------
// Stage B: 32 independent 512x512x512 fp32 GEMMs.
//   typ=0 (NT): VaIn[i,j]  = sum_k Ein[i,k] * Vin[j,k]
//   typ=1 (TN): VaOut[i,j] = sum_k Eo[k,i]  * Vout[k,j]
// 128x128 tile, KB=8, 8x8 per thread, register-prefetch double-buffered smem.
// ---------------------------------------------------------------------------
__global__ __launch_bounds__(256) void kb_gemm()
{
    const int z   = blockIdx.z;
    const int typ = z >> 4;        // 0 in / 1 out
    const int mh  = z & 15;        // b*8+h
    const float* __restrict__ A  = (typ ? g_Eo   : g_Ein ) + mh*NN;
    const float* __restrict__ Bm = (typ ? g_Vout : g_Vin ) + mh*NN;
    float*       __restrict__ C  = (typ ? g_VaOut: g_VaIn) + mh*NN;
    const int it = blockIdx.y * 128;
    const int jt = blockIdx.x * 128;

    __shared__ __align__(16) float As[2][8][132];
    __shared__ __align__(16) float Bs[2][8][132];

    const int t  = threadIdx.x;
    const int tx = t & 15, ty = t >> 4;

    float acc[8][8];
    #pragma unroll
    for (int u = 0; u < 8; u++)
        #pragma unroll
        for (int v = 0; v < 8; v++) acc[u][v] = 0.f;

    const int kk_l = t >> 5, i4_l = (t & 31) << 2;   // TN loader indices
    const int ii_l = t >> 1, k4_l = (t & 1) << 2;    // NT loader indices

    float4 ra, rb;
    if (typ){
        ra = *reinterpret_cast<const float4*>(&A [kk_l*Nn + it + i4_l]);
        rb = *reinterpret_cast<const float4*>(&Bm[kk_l*Nn + jt + i4_l]);
        *reinterpret_cast<float4*>(&As[0][kk_l][i4_l]) = ra;
        *reinterpret_cast<float4*>(&Bs[0][kk_l][i4_l]) = rb;
    } else {
        ra = *reinterpret_cast<const float4*>(&A [(it+ii_l)*Nn + k4_l]);
        rb = *reinterpret_cast<const float4*>(&Bm[(jt+ii_l)*Nn + k4_l]);
        As[0][k4_l+0][ii_l]=ra.x; As[0][k4_l+1][ii_l]=ra.y; As[0][k4_l+2][ii_l]=ra.z; As[0][k4_l+3][ii_l]=ra.w;
        Bs[0][k4_l+0][ii_l]=rb.x; Bs[0][k4_l+1][ii_l]=rb.y; Bs[0][k4_l+2][ii_l]=rb.z; Bs[0][k4_l+3][ii_l]=rb.w;
    }
    __syncthreads();

    int buf = 0;
    for (int k0 = 0; k0 < Nn; k0 += 8){
        const bool has_next = (k0 + 8 < Nn);
        if (has_next){
            const int kn = k0 + 8;
            if (typ){
                ra = *reinterpret_cast<const float4*>(&A [(kn+kk_l)*Nn + it + i4_l]);
                rb = *reinterpret_cast<const float4*>(&Bm[(kn+kk_l)*Nn + jt + i4_l]);
            } else {
                ra = *reinterpret_cast<const float4*>(&A [(it+ii_l)*Nn + kn + k4_l]);
                rb = *reinterpret_cast<const float4*>(&Bm[(jt+ii_l)*Nn + kn + k4_l]);
            }
        }
        #pragma unroll
        for (int kk = 0; kk < 8; kk++){
            float ar[8], br[8];
            float4 a0 = *reinterpret_cast<const float4*>(&As[buf][kk][ty*8    ]);
            float4 a1 = *reinterpret_cast<const float4*>(&As[buf][kk][ty*8 + 4]);
            float4 b0 = *reinterpret_cast<const float4*>(&Bs[buf][kk][tx*8    ]);
            float4 b1 = *reinterpret_cast<const float4*>(&Bs[buf][kk][tx*8 + 4]);
            ar[0]=a0.x;ar[1]=a0.y;ar[2]=a0.z;ar[3]=a0.w;ar[4]=a1.x;ar[5]=a1.y;ar[6]=a1.z;ar[7]=a1.w;
            br[0]=b0.x;br[1]=b0.y;br[2]=b0.z;br[3]=b0.w;br[4]=b1.x;br[5]=b1.y;br[6]=b1.z;br[7]=b1.w;
            #pragma unroll
            for (int u = 0; u < 8; u++)
                #pragma unroll
                for (int v = 0; v < 8; v++)
                    acc[u][v] = fmaf(ar[u], br[v], acc[u][v]);
        }
        if (has_next){
            const int nb = buf ^ 1;
            if (typ){
                *reinterpret_cast<float4*>(&As[nb][kk_l][i4_l]) = ra;
                *reinterpret_cast<float4*>(&Bs[nb][kk_l][i4_l]) = rb;
            } else {
                As[nb][k4_l+0][ii_l]=ra.x; As[nb][k4_l+1][ii_l]=ra.y; As[nb][k4_l+2][ii_l]=ra.z; As[nb][k4_l+3][ii_l]=ra.w;
                Bs[nb][k4_l+0][ii_l]=rb.x; Bs[nb][k4_l+1][ii_l]=rb.y; Bs[nb][k4_l+2][ii_l]=rb.z; Bs[nb][k4_l+3][ii_l]=rb.w;
            }
        }
        __syncthreads();
        buf ^= 1;
    }

    #pragma unroll
    for (int u = 0; u < 8; u++){
        const int row = it + ty*8 + u;
        float4 q0 = make_float4(acc[u][0],acc[u][1],acc[u][2],acc[u][3]);
        float4 q1 = make_float4(acc[u][4],acc[u][5],acc[u][6],acc[u][7]);
        *reinterpret_cast<float4*>(&C[row*Nn + jt + tx*8    ]) = q0;
        *reinterpret_cast<float4*>(&C[row*Nn + jt + tx*8 + 4]) = q1;
    }
}

// ---------------------------------------------------------------------------
// Stage C: O = Va @ Wo + bo, out = sigmoid(O[:,:128]) * O[:,128:]
// ---------------------------------------------------------------------------
__global__ __launch_bounds__(256) void kc_out(
    const float* __restrict__ Wo, const float* __restrict__ bo,
    float* __restrict__ out)
{
    __shared__ float sVa[32][16];     // [jl][v]
    __shared__ float sWo[16][256];
    __shared__ float sbo[256];

    const int t  = threadIdx.x;
    const int b  = blockIdx.z;
    const int i  = blockIdx.y;
    const int j0 = blockIdx.x * 32;

    #pragma unroll
    for (int q = 0; q < 16; q++){
        int idx = q*256 + t;
        sWo[idx >> 8][idx & 255] = Wo[idx];
    }
    sbo[t] = bo[t];
    #pragma unroll
    for (int p = 0; p < 2; p++){
        int idx = p*256 + t;
        int v = idx >> 5, jl = idx & 31;
        const float* src = (v < 8) ? (g_VaIn  + (b*Hh + v    )*NN)
                                   : (g_VaOut + (b*Hh + v - 8)*NN);
        sVa[jl][v] = src[i*Nn + j0 + jl];
    }
    __syncthreads();

    const int c  = t & 127;
    const int rp = t >> 7;
    float wg[16], wl[16];
    #pragma unroll
    for (int v = 0; v < 16; v++){ wg[v] = sWo[v][c]; wl[v] = sWo[v][c+128]; }
    const float bg = sbo[c], bl = sbo[c+128];

    float* op = out + (size_t)((b*Nn + i)*Nn + j0) * Cc + c;
    #pragma unroll
    for (int q = 0; q < 16; q++){
        const int r = rp*16 + q;
        float g = bg, l = bl;
        #pragma unroll
        for (int v = 0; v < 16; v++){
            float va = sVa[r][v];
            g = fmaf(va, wg[v], g);
            l = fmaf(va, wl[v], l);
        }
        op[(size_t)r * Cc] = sigmoidf_(g) * l;
    }
}

// ---------------------------------------------------------------------------
extern "C" void kernel_launch(void* const* d_in, const int* in_sizes, int n_in,
                              void* d_out, int out_size)
{
    const float* e    = (const float*)d_in[0];
    const float* mask = (const float*)d_in[1];
    const float* lnw  = (const float*)d_in[2];
    const float* lnb  = (const float*)d_in[3];
    const float* Wv   = (const float*)d_in[4];
    const float* bv   = (const float*)d_in[5];
    const float* We   = (const float*)d_in[6];
    const float* be   = (const float*)d_in[7];
    const float* Wo   = (const float*)d_in[8];
    const float* bo   = (const float*)d_in[9];
    float* out = (float*)d_out;

    ka_fused<<<2048, 256>>>(e, mask, lnw, lnb, Wv, bv, We, be);
    kb_gemm <<<dim3(4, 4, 32), 256>>>();
    kc_out  <<<dim3(16, 512, 2), 256>>>(Wo, bo, out);
}

// round 6
// speedup vs baseline: 1.8854x; 1.3108x over previous
#include <cuda_runtime.h>
#include <cuda_bf16.h>
#include <math.h>
#include <stdint.h>

typedef unsigned int u32;
typedef unsigned long long u64;

#define Nn 512
#define Cc 128
#define Hh 8
#define Bb 2
#define NN (Nn*Nn)
#define SZ (Bb*Hh*NN)

// ---------------- scratch (device globals; no runtime allocation) ----------
__device__ __align__(16) __nv_bfloat16 g_Vin_h [SZ];
__device__ __align__(16) __nv_bfloat16 g_Vin_l [SZ];
__device__ __align__(16) __nv_bfloat16 g_Vout_h[SZ];
__device__ __align__(16) __nv_bfloat16 g_Vout_l[SZ];
__device__ __align__(16) __nv_bfloat16 g_Ein_h [SZ];
__device__ __align__(16) __nv_bfloat16 g_Ein_l [SZ];
__device__ __align__(16) __nv_bfloat16 g_Eo_h  [SZ];
__device__ __align__(16) __nv_bfloat16 g_Eo_l  [SZ];
__device__ __align__(16) float g_VaIn [SZ];
__device__ __align__(16) float g_VaOut[SZ];

__device__ __forceinline__ float sigmoidf_(float x){ return 1.f/(1.f + __expf(-x)); }

__device__ __forceinline__ u32 smem_u32(const void* p){
    u32 a;
    asm("{ .reg .u64 t; cvta.to.shared.u64 t, %1; cvt.u32.u64 %0, t; }" : "=r"(a) : "l"(p));
    return a;
}
__device__ __forceinline__ void cpa16(u32 dst, const void* src){
    asm volatile("cp.async.cg.shared.global [%0], [%1], 16;" :: "r"(dst), "l"(src));
}
__device__ __forceinline__ void cpa_commit(){ asm volatile("cp.async.commit_group;"); }
__device__ __forceinline__ void cpa_wait1(){ asm volatile("cp.async.wait_group 1;"); }
__device__ __forceinline__ void cpa_wait0(){ asm volatile("cp.async.wait_group 0;"); }
__device__ __forceinline__ void ldm4(u32* r, u32 a){
    asm volatile("ldmatrix.sync.aligned.m8n8.x4.shared.b16 {%0,%1,%2,%3}, [%4];"
        : "=r"(r[0]),"=r"(r[1]),"=r"(r[2]),"=r"(r[3]) : "r"(a));
}
__device__ __forceinline__ void ldm4t(u32* r, u32 a){
    asm volatile("ldmatrix.sync.aligned.m8n8.x4.trans.shared.b16 {%0,%1,%2,%3}, [%4];"
        : "=r"(r[0]),"=r"(r[1]),"=r"(r[2]),"=r"(r[3]) : "r"(a));
}
__device__ __forceinline__ void mma16816(float* c, const u32* a, const u32* b){
    asm volatile("mma.sync.aligned.m16n8k16.row.col.f32.bf16.bf16.f32 "
        "{%0,%1,%2,%3}, {%4,%5,%6,%7}, {%8,%9}, {%0,%1,%2,%3};"
        : "+f"(c[0]), "+f"(c[1]), "+f"(c[2]), "+f"(c[3])
        : "r"(a[0]), "r"(a[1]), "r"(a[2]), "r"(a[3]), "r"(b[0]), "r"(b[1]));
}

// ---------------------------------------------------------------------------
// Stage A: LN + dual projection + gating; outputs split-bf16 (hi/lo) planes.
// ---------------------------------------------------------------------------
__global__ __launch_bounds__(256) void ka_fused(
    const float* __restrict__ e, const float* __restrict__ mask,
    const float* __restrict__ lnw, const float* __restrict__ lnb,
    const float* __restrict__ Wv, const float* __restrict__ bv,
    const float* __restrict__ We, const float* __restrict__ be)
{
    __shared__ __align__(16) float es[16][260];
    __shared__ __align__(16) float ws[16][68];
    __shared__ float smu[256], srs[256];

    const int t  = threadIdx.x;
    const int R0 = blockIdx.x * 256;

    {   // LN stats: thread t owns row R0+t
        const float4* erow = reinterpret_cast<const float4*>(e + (size_t)(R0 + t)*128);
        float s = 0.f, sq = 0.f;
        #pragma unroll
        for (int q = 0; q < 32; q++){
            float4 v = erow[q];
            s  += v.x + v.y + v.z + v.w;
            sq += v.x*v.x + v.y*v.y + v.z*v.z + v.w*v.w;
        }
        float mu  = s * (1.f/128.f);
        float var = sq * (1.f/128.f) - mu*mu;
        smu[t] = mu;
        srs[t] = rsqrtf(var + 1e-5f);
    }
    __syncthreads();

    const int tx = t & 15, ty = t >> 4;

    float acc[16][4];
    #pragma unroll
    for (int u = 0; u < 16; u++){ acc[u][0]=0.f; acc[u][1]=0.f; acc[u][2]=0.f; acc[u][3]=0.f; }

    for (int c0 = 0; c0 < 128; c0 += 16){
        #pragma unroll
        for (int q = 0; q < 4; q++){
            int idx = q*256 + t;
            int rl = idx >> 2, c4 = idx & 3;
            float4 v = *reinterpret_cast<const float4*>(e + (size_t)(R0+rl)*128 + c0 + c4*4);
            float mu = smu[rl], rs = srs[rl];
            float4 w4 = *reinterpret_cast<const float4*>(lnw + c0 + c4*4);
            float4 b4 = *reinterpret_cast<const float4*>(lnb + c0 + c4*4);
            es[c4*4+0][rl] = (v.x - mu)*rs*w4.x + b4.x;
            es[c4*4+1][rl] = (v.y - mu)*rs*w4.y + b4.y;
            es[c4*4+2][rl] = (v.z - mu)*rs*w4.z + b4.z;
            es[c4*4+3][rl] = (v.w - mu)*rs*w4.w + b4.w;
        }
        #pragma unroll
        for (int q = 0; q < 4; q++){
            int idx = q*256 + t;
            int kk = idx >> 6, j = idx & 63;
            int aa = j >> 4, hh = (j >> 1) & 7, p = j & 1;
            const float* Wm = (aa < 2) ? Wv : We;
            int sc = ((aa & 1) << 4) + (p << 3) + hh;
            ws[kk][j] = Wm[(c0 + kk)*32 + sc];
        }
        __syncthreads();

        #pragma unroll
        for (int kk = 0; kk < 16; kk++){
            float4 bf = *reinterpret_cast<const float4*>(&ws[kk][tx*4]);
            float4 a0 = *reinterpret_cast<const float4*>(&es[kk][ty*16     ]);
            float4 a1 = *reinterpret_cast<const float4*>(&es[kk][ty*16 +  4]);
            float4 a2 = *reinterpret_cast<const float4*>(&es[kk][ty*16 +  8]);
            float4 a3 = *reinterpret_cast<const float4*>(&es[kk][ty*16 + 12]);
            float av[16] = {a0.x,a0.y,a0.z,a0.w, a1.x,a1.y,a1.z,a1.w,
                            a2.x,a2.y,a2.z,a2.w, a3.x,a3.y,a3.z,a3.w};
            #pragma unroll
            for (int u = 0; u < 16; u++){
                acc[u][0] = fmaf(av[u], bf.x, acc[u][0]);
                acc[u][1] = fmaf(av[u], bf.y, acc[u][1]);
                acc[u][2] = fmaf(av[u], bf.z, acc[u][2]);
                acc[u][3] = fmaf(av[u], bf.w, acc[u][3]);
            }
        }
        __syncthreads();
    }

    // Gating epilogue -> split bf16
    const int a  = tx >> 2;
    const int h0 = (tx & 3) * 2;
    __nv_bfloat16* dh = (a==0) ? g_Vin_h : (a==1) ? g_Vout_h : (a==2) ? g_Ein_h : g_Eo_h;
    __nv_bfloat16* dl = (a==0) ? g_Vin_l : (a==1) ? g_Vout_l : (a==2) ? g_Ein_l : g_Eo_l;
    const float* bm = (a < 2) ? bv : be;
    const int sbase = (a & 1) << 4;
    const float bg0 = bm[sbase + h0],     bl0 = bm[sbase + 8 + h0];
    const float bg1 = bm[sbase + h0 + 1], bl1 = bm[sbase + 8 + h0 + 1];
    const int bbk  = R0 >> 18;                       // NN = 2^18
    const int rl0  = (R0 & (NN-1)) + ty*16;
    const size_t base0 = (size_t)(bbk*Hh + h0)*NN + rl0;
    const size_t base1 = base0 + NN;

    union U4 { uint2 u; __nv_bfloat16 h[4]; };
    U4 H0, L0, H1, L1;
    #pragma unroll
    for (int u = 0; u < 16; u++){
        float mk = mask[R0 + ty*16 + u];
        float o0 = sigmoidf_(acc[u][0] + bg0 + mk) * (acc[u][1] + bl0);
        float o1 = sigmoidf_(acc[u][2] + bg1 + mk) * (acc[u][3] + bl1);
        __nv_bfloat16 h0v = __float2bfloat16(o0);
        __nv_bfloat16 l0v = __float2bfloat16(o0 - __bfloat162float(h0v));
        __nv_bfloat16 h1v = __float2bfloat16(o1);
        __nv_bfloat16 l1v = __float2bfloat16(o1 - __bfloat162float(h1v));
        H0.h[u&3] = h0v; L0.h[u&3] = l0v; H1.h[u&3] = h1v; L1.h[u&3] = l1v;
        if ((u & 3) == 3){
            *reinterpret_cast<uint2*>(&dh[base0 + u - 3]) = H0.u;
            *reinterpret_cast<uint2*>(&dl[base0 + u - 3]) = L0.u;
            *reinterpret_cast<uint2*>(&dh[base1 + u - 3]) = H1.u;
            *reinterpret_cast<uint2*>(&dl[base1 + u - 3]) = L1.u;
        }
    }
}

// ---------------------------------------------------------------------------
// Stage B: 32x (512^3) GEMM via mma.sync bf16 (split hi/lo, 3 products,
// fp32 accum). cp.async double-buffered K32 chunks.
//   typ=0 (NT): VaIn[i,j]  = sum_k Ein[i,k]*Vin[j,k]   smem [row][k], ldmatrix
//   typ=1 (TN): VaOut[i,j] = sum_k Eo[k,i]*Vout[k,j]   smem [k][col], ldmatrix.trans
// Block: C tile 128x128, 8 warps (2x4), warp tile 64x32, frags 4x4 m16n8k16.
// ---------------------------------------------------------------------------
#define T_NT 5120          // 128*40 bf16 elems per tile
#define T_TN 4352          // 32*136
#define KB_SMEM (2*4*T_NT*2)   // 81920 B (NT is larger)

__global__ __launch_bounds__(256) void kb_mma()
{
    extern __shared__ __align__(16) char dsm[];
    const int t    = threadIdx.x;
    const int wid  = t >> 5;
    const int lane = t & 31;
    const int lr   = lane & 7;
    const int lg   = lane >> 3;
    const int z    = blockIdx.z;
    const int typ  = z >> 4;
    const int mh   = z & 15;
    const size_t off = (size_t)mh * NN;
    const int it = blockIdx.y * 128;
    const int jt = blockIdx.x * 128;
    const int wm = (wid & 1) * 64;
    const int wn = (wid >> 1) * 32;

    const __nv_bfloat16 *tg0, *tg1, *tg2, *tg3;
    float* Cg;
    if (typ == 0){ tg0 = g_Ein_h + off; tg1 = g_Ein_l + off; tg2 = g_Vin_h  + off; tg3 = g_Vin_l  + off; Cg = g_VaIn  + off; }
    else         { tg0 = g_Eo_h  + off; tg1 = g_Eo_l  + off; tg2 = g_Vout_h + off; tg3 = g_Vout_l + off; Cg = g_VaOut + off; }
    const __nv_bfloat16* tg[4] = {tg0, tg1, tg2, tg3};

    const u32 s0 = smem_u32(dsm);
    const int T  = typ ? T_TN : T_NT;
    const int ld = typ ? 136 : 40;

    float acc[4][4][4];
    #pragma unroll
    for (int a = 0; a < 4; a++)
        #pragma unroll
        for (int b = 0; b < 4; b++){
            acc[a][b][0]=0.f; acc[a][b][1]=0.f; acc[a][b][2]=0.f; acc[a][b][3]=0.f;
        }

    // ---- chunk loader (cp.async) ----
    auto load_chunk = [&](int ks, int buf){
        const int bo = buf * 4 * T;
        if (typ == 0){
            #pragma unroll
            for (int q = 0; q < 8; q++){
                int idx  = q*256 + t;
                int tile = idx >> 9;
                int rem  = idx & 511;
                int r    = rem >> 2, seg = rem & 3;
                int rb   = (tile < 2) ? it : jt;
                cpa16(s0 + (u32)(bo + tile*T + r*40 + seg*8)*2,
                      tg[tile] + (size_t)(rb + r)*Nn + ks + seg*8);
            }
        } else {
            #pragma unroll
            for (int q = 0; q < 8; q++){
                int idx  = q*256 + t;
                int tile = idx >> 9;
                int rem  = idx & 511;
                int r    = rem >> 4, seg = rem & 15;
                int cb   = (tile < 2) ? it : jt;
                cpa16(s0 + (u32)(bo + tile*T + r*136 + seg*8)*2,
                      tg[tile] + (size_t)(ks + r)*Nn + cb + seg*8);
            }
        }
        cpa_commit();
    };

    load_chunk(0, 0);

    for (int c = 0; c < 16; c++){
        if (c < 15){ load_chunk((c+1)*32, (c+1) & 1); cpa_wait1(); }
        else       { cpa_wait0(); }
        __syncthreads();

        const int bo = (c & 1) * 4 * T;
        const u32 AH = s0 + (u32)(bo        )*2;
        const u32 AL = s0 + (u32)(bo +   T  )*2;
        const u32 BH = s0 + (u32)(bo + 2*T  )*2;
        const u32 BL = s0 + (u32)(bo + 3*T  )*2;

        #pragma unroll
        for (int k16 = 0; k16 < 2; k16++){
            const int ks16 = k16 * 16;
            u32 bh[4][2], bl_[4][2];
            // B fragments: 2 x ldmatrix.x4 per plane (covers 4 n-frags)
            #pragma unroll
            for (int nf2 = 0; nf2 < 2; nf2++){
                u32 r4[4];
                u32 offb;
                if (typ == 0){
                    int rowB = wn + nf2*16 + ((lg >= 2) ? 8 : 0) + lr;
                    int colB = ks16 + ((lg & 1) ? 8 : 0);
                    offb = (u32)(rowB*ld + colB)*2;
                } else {
                    int rowB = ks16 + ((lg & 1) ? 8 : 0) + lr;
                    int colB = wn + nf2*16 + ((lg >= 2) ? 8 : 0);
                    offb = (u32)(rowB*ld + colB)*2;
                }
                if (typ == 0) ldm4(r4, BH + offb); else ldm4t(r4, BH + offb);
                bh[nf2*2][0]=r4[0]; bh[nf2*2][1]=r4[1]; bh[nf2*2+1][0]=r4[2]; bh[nf2*2+1][1]=r4[3];
                if (typ == 0) ldm4(r4, BL + offb); else ldm4t(r4, BL + offb);
                bl_[nf2*2][0]=r4[0]; bl_[nf2*2][1]=r4[1]; bl_[nf2*2+1][0]=r4[2]; bl_[nf2*2+1][1]=r4[3];
            }
            // A fragments per m-frag, then 3-product MMAs
            #pragma unroll
            for (int mf = 0; mf < 4; mf++){
                u32 ah[4], al[4];
                u32 offa;
                if (typ == 0){
                    int rowA = wm + mf*16 + (lane & 15);
                    int colA = ks16 + ((lane >> 4) ? 8 : 0);
                    offa = (u32)(rowA*ld + colA)*2;
                    ldm4(ah, AH + offa);
                    ldm4(al, AL + offa);
                } else {
                    int rowA = ks16 + ((lg & 2) ? 8 : 0) + lr;
                    int colA = wm + mf*16 + ((lg & 1) ? 8 : 0);
                    offa = (u32)(rowA*ld + colA)*2;
                    ldm4t(ah, AH + offa);
                    ldm4t(al, AL + offa);
                }
                #pragma unroll
                for (int nf = 0; nf < 4; nf++){
                    mma16816(acc[mf][nf], ah, bh[nf]);
                    mma16816(acc[mf][nf], ah, bl_[nf]);
                    mma16816(acc[mf][nf], al, bh[nf]);
                }
            }
        }
        __syncthreads();
    }

    // Epilogue: direct fp32 stores (float2 per fragment row)
    const int g   = lane >> 2;
    const int tig = lane & 3;
    #pragma unroll
    for (int mf = 0; mf < 4; mf++){
        #pragma unroll
        for (int nf = 0; nf < 4; nf++){
            int row = it + wm + mf*16 + g;
            int col = jt + wn + nf*8 + tig*2;
            float2 v0 = make_float2(acc[mf][nf][0], acc[mf][nf][1]);
            float2 v1 = make_float2(acc[mf][nf][2], acc[mf][nf][3]);
            *reinterpret_cast<float2*>(&Cg[(size_t)row*Nn + col])       = v0;
            *reinterpret_cast<float2*>(&Cg[(size_t)(row+8)*Nn + col])   = v1;
        }
    }
}

// ---------------------------------------------------------------------------
// Stage C: O = Va @ Wo + bo, out = sigmoid(O[:,:128]) * O[:,128:]
// One block per (b,i) row: Wo loaded ONCE, held in registers; Va double-buffered.
// ---------------------------------------------------------------------------
__global__ __launch_bounds__(256) void kc_out(
    const float* __restrict__ Wo, const float* __restrict__ bo,
    float* __restrict__ out)
{
    __shared__ float sVa[2][32][17];
    __shared__ float sWo[16][256];
    __shared__ float sbo[256];

    const int t = threadIdx.x;
    const int i = blockIdx.x;
    const int b = blockIdx.y;

    #pragma unroll
    for (int q = 0; q < 16; q++){
        int idx = q*256 + t;
        sWo[idx >> 8][idx & 255] = Wo[idx];
    }
    sbo[t] = bo[t];

    #pragma unroll
    for (int p = 0; p < 2; p++){
        int idx = p*256 + t;
        int v = idx >> 5, jl = idx & 31;
        const float* src = (v < 8) ? (g_VaIn  + (size_t)(b*Hh + v    )*NN)
                                   : (g_VaOut + (size_t)(b*Hh + v - 8)*NN);
        sVa[0][jl][v] = src[(size_t)i*Nn + jl];
    }
    __syncthreads();

    const int c  = t & 127;
    const int rp = t >> 7;
    float wg[16], wl[16];
    #pragma unroll
    for (int v = 0; v < 16; v++){ wg[v] = sWo[v][c]; wl[v] = sWo[v][c+128]; }
    const float bg = sbo[c], bl = sbo[c+128];

    int buf = 0;
    for (int jc = 0; jc < 16; jc++){
        if (jc + 1 < 16){
            #pragma unroll
            for (int p = 0; p < 2; p++){
                int idx = p*256 + t;
                int v = idx >> 5, jl = idx & 31;
                const float* src = (v < 8) ? (g_VaIn  + (size_t)(b*Hh + v    )*NN)
                                           : (g_VaOut + (size_t)(b*Hh + v - 8)*NN);
                sVa[buf^1][jl][v] = src[(size_t)i*Nn + (jc+1)*32 + jl];
            }
        }
        float* op = out + ((size_t)(b*Nn + i)*Nn + jc*32) * Cc + c;
        #pragma unroll
        for (int q = 0; q < 16; q++){
            const int jl = rp*16 + q;
            float g = bg, l = bl;
            #pragma unroll
            for (int v = 0; v < 16; v++){
                float va = sVa[buf][jl][v];
                g = fmaf(va, wg[v], g);
                l = fmaf(va, wl[v], l);
            }
            op[(size_t)jl * Cc] = sigmoidf_(g) * l;
        }
        __syncthreads();
        buf ^= 1;
    }
}

// ---------------------------------------------------------------------------
extern "C" void kernel_launch(void* const* d_in, const int* in_sizes, int n_in,
                              void* d_out, int out_size)
{
    const float* e    = (const float*)d_in[0];
    const float* mask = (const float*)d_in[1];
    const float* lnw  = (const float*)d_in[2];
    const float* lnb  = (const float*)d_in[3];
    const float* Wv   = (const float*)d_in[4];
    const float* bv   = (const float*)d_in[5];
    const float* We   = (const float*)d_in[6];
    const float* be   = (const float*)d_in[7];
    const float* Wo   = (const float*)d_in[8];
    const float* bo   = (const float*)d_in[9];
    float* out = (float*)d_out;

    cudaFuncSetAttribute(kb_mma, cudaFuncAttributeMaxDynamicSharedMemorySize, KB_SMEM);

    ka_fused<<<2048, 256>>>(e, mask, lnw, lnb, Wv, bv, We, be);
    kb_mma  <<<dim3(4, 4, 32), 256, KB_SMEM>>>();
    kc_out  <<<dim3(512, 2), 256>>>(Wo, bo, out);
}